// round 2
// baseline (speedup 1.0000x reference)
#include <cuda_runtime.h>
#include <cstdint>

// Inputs (metadata order):
//   d_in[0] = g     : float32 [N, N]   (N*N elements)
//   d_in[1] = h     : float32 [n, D]   (n*D elements)
//   d_in[2] = pre_h : float32 [N, D]   (N*D elements)  (unused)
//   d_in[3] = idx   : int32   [n]      (JAX default x64 disabled -> int32!)
// Output: reference returns (g, new_h). Handle concat / new_h-only / g-only
// layouts by branching on out_size (host-side, graph-safe).

__global__ void zero_f4_kernel(float4* __restrict__ p, long long n4) {
    long long i = (long long)blockIdx.x * blockDim.x + threadIdx.x;
    if (i < n4) {
        p[i] = make_float4(0.f, 0.f, 0.f, 0.f);
    }
}

// One thread per float4 of h: n rows * (D/4) float4s per row.
// new_h[idx[row]] = h[row]
__global__ void scatter_rows_f4_kernel(const float4* __restrict__ h,
                                       const int* __restrict__ idx,
                                       float4* __restrict__ new_h,
                                       long long total_f4, int d4) {
    long long t = (long long)blockIdx.x * blockDim.x + threadIdx.x;
    if (t >= total_f4) return;
    long long row = t / d4;
    int c = (int)(t - row * (long long)d4);
    long long dst_row = (long long)idx[row];
    new_h[dst_row * (long long)d4 + c] = h[t];
}

// Wide vectorized copy (fallback / explicit SM copy for g passthrough).
__global__ void copy_f4_kernel(const float4* __restrict__ src,
                               float4* __restrict__ dst, long long n4) {
    long long i = (long long)blockIdx.x * blockDim.x + threadIdx.x;
    long long stride = (long long)gridDim.x * blockDim.x;
    for (; i < n4; i += stride) {
        dst[i] = src[i];
    }
}

extern "C" void kernel_launch(void* const* d_in, const int* in_sizes, int n_in,
                              void* d_out, int out_size) {
    const float* g   = (const float*)d_in[0];
    const float* h   = (const float*)d_in[1];
    const int*   idx = (const int*)d_in[3];

    long long g_elems  = (long long)in_sizes[0];   // N*N
    long long h_elems  = (long long)in_sizes[1];   // n*D
    long long ph_elems = (long long)in_sizes[2];   // N*D
    long long n_idx    = (long long)in_sizes[3];   // n

    int D  = (int)(h_elems / n_idx);               // 256
    int d4 = D / 4;                                // 64

    long long osz = (long long)out_size;

    bool has_g    = false;
    bool has_newh = false;
    float* out_g    = nullptr;
    float* out_newh = nullptr;

    if (osz >= g_elems + ph_elems) {
        has_g = true; has_newh = true;
        out_g = (float*)d_out;
        out_newh = out_g + g_elems;
    } else if (osz >= g_elems) {
        has_g = true;
        out_g = (float*)d_out;
    } else {
        has_newh = true;
        out_newh = (float*)d_out;
    }

    if (has_g) {
        cudaMemcpyAsync(out_g, g, g_elems * sizeof(float),
                        cudaMemcpyDeviceToDevice);
    }

    if (has_newh) {
        // Zero new_h region (N*D floats).
        long long n4 = ph_elems / 4;
        int threads = 256;
        long long blocks = (n4 + threads - 1) / threads;
        zero_f4_kernel<<<(unsigned)blocks, threads>>>((float4*)out_newh, n4);

        // Scatter h rows into new_h at idx.
        long long total_f4 = n_idx * (long long)d4;
        long long sblocks = (total_f4 + threads - 1) / threads;
        scatter_rows_f4_kernel<<<(unsigned)sblocks, threads>>>(
            (const float4*)h, idx, (float4*)out_newh, total_f4, d4);
    }
}

// round 3
// speedup vs baseline: 1.9206x; 1.9206x over previous
#include <cuda_runtime.h>
#include <cstdint>

// Inputs (metadata order):
//   d_in[0] = g     : float32 [N, N]   (N*N elements)
//   d_in[1] = h     : float32 [n, D]   (n*D elements)
//   d_in[2] = pre_h : float32 [N, D]   (N*D elements)  (unused)
//   d_in[3] = idx   : int32   [n]      (sorted unique)
// Output: concat( g [N*N], new_h [N*D] ) float32 (layout detected from out_size).

// ---------------------------------------------------------------------------
// Wide SM copy: grid-stride, 4 independent float4 loads per iteration (MLP=4).
// Targets the LTS path-independent ~6300 B/cyc chip cap.
// ---------------------------------------------------------------------------
__global__ void copy_f4_mlp4_kernel(const float4* __restrict__ src,
                                    float4* __restrict__ dst, long long n4) {
    long long stride = (long long)gridDim.x * blockDim.x;
    long long i = (long long)blockIdx.x * blockDim.x + threadIdx.x;

    // Main loop: 4 independent float4s in flight per thread.
    long long limit = n4 - 3 * stride;
    for (; i < limit; i += 4 * stride) {
        float4 a = src[i];
        float4 b = src[i + stride];
        float4 c = src[i + 2 * stride];
        float4 d = src[i + 3 * stride];
        dst[i]              = a;
        dst[i + stride]     = b;
        dst[i + 2 * stride] = c;
        dst[i + 3 * stride] = d;
    }
    // Tail.
    for (; i < n4; i += stride) {
        dst[i] = src[i];
    }
}

// ---------------------------------------------------------------------------
// Fused new_h fill: one thread per output float4 (N rows * D/4 cols).
// Binary search sorted idx: if row r == idx[j], write h[j]; else write zeros.
// Each output byte written exactly once (no zero-then-overwrite).
// ---------------------------------------------------------------------------
__global__ void fill_newh_kernel(const float4* __restrict__ h,
                                 const int* __restrict__ idx,
                                 float4* __restrict__ new_h,
                                 int n_idx, int d4, long long total_f4) {
    long long t = (long long)blockIdx.x * blockDim.x + threadIdx.x;
    if (t >= total_f4) return;
    int r = (int)(t / d4);
    int c = (int)(t - (long long)r * d4);

    // Binary search for r in idx[0..n_idx).
    int lo = 0, hi = n_idx;
    while (lo < hi) {
        int mid = (lo + hi) >> 1;
        if (idx[mid] < r) lo = mid + 1;
        else hi = mid;
    }
    float4 v = make_float4(0.f, 0.f, 0.f, 0.f);
    if (lo < n_idx && idx[lo] == r) {
        v = h[(long long)lo * d4 + c];
    }
    new_h[t] = v;
}

extern "C" void kernel_launch(void* const* d_in, const int* in_sizes, int n_in,
                              void* d_out, int out_size) {
    const float* g   = (const float*)d_in[0];
    const float* h   = (const float*)d_in[1];
    const int*   idx = (const int*)d_in[3];

    long long g_elems  = (long long)in_sizes[0];   // N*N
    long long h_elems  = (long long)in_sizes[1];   // n*D
    long long ph_elems = (long long)in_sizes[2];   // N*D
    long long n_idx    = (long long)in_sizes[3];   // n

    int D  = (int)(h_elems / n_idx);               // 256
    int d4 = D / 4;                                // 64

    long long osz = (long long)out_size;

    bool has_g = false, has_newh = false;
    float* out_g = nullptr;
    float* out_newh = nullptr;

    if (osz >= g_elems + ph_elems) {
        has_g = true; has_newh = true;
        out_g = (float*)d_out;
        out_newh = out_g + g_elems;
    } else if (osz >= g_elems) {
        has_g = true;
        out_g = (float*)d_out;
    } else {
        has_newh = true;
        out_newh = (float*)d_out;
    }

    if (has_newh) {
        long long total_f4 = ph_elems / 4;       // N * D/4
        int threads = 256;
        long long blocks = (total_f4 + threads - 1) / threads;
        fill_newh_kernel<<<(unsigned)blocks, threads>>>(
            (const float4*)h, idx, (float4*)out_newh,
            (int)n_idx, d4, total_f4);
    }

    if (has_g) {
        long long n4 = g_elems / 4;              // 100M float4s
        int threads = 256;
        // Full-chip persistent-ish grid: 148 SMs * 8 blocks of 256 thr.
        int blocks = 148 * 8;
        copy_f4_mlp4_kernel<<<blocks, threads>>>(
            (const float4*)g, (float4*)out_g, n4);
    }
}